// round 1
// baseline (speedup 1.0000x reference)
#include <cuda_runtime.h>
#include <math.h>

#define OUTSZ 260
#define IMGW  2048
#define IMGH  2048
#define TAPS  6

__device__ __forceinline__ float lanczos_w(float d) {
    float ad = fabsf(d);
    if (ad >= 3.0f) return 0.0f;
    if (ad < 1e-8f) return 1.0f;
    const float PI = 3.14159265358979323846f;
    float pd = PI * d;
    // sinc(d)*sinc(d/3) = sin(pi d) * sin(pi d / 3) * 3 / (pi^2 d^2)
    return sinpif(d) * sinpif(d * (1.0f / 3.0f)) * (3.0f / (pd * pd));
}

__global__ __launch_bounds__(384)
void crop_resize_kernel(const float* __restrict__ scores,
                        const float* __restrict__ boxes,
                        const float* __restrict__ img,
                        float* __restrict__ out) {
    const int p   = blockIdx.x;   // output row 0..259
    const int box = blockIdx.y;   // 0..9

    // ---- box params (computed redundantly per thread; broadcast loads) ----
    const float b0 = boxes[box * 4 + 0];
    const float b1 = boxes[box * 4 + 1];
    const float b2 = boxes[box * 4 + 2];
    const float b3 = boxes[box * 4 + 3];
    // XLA f32->s32 convert truncates toward zero; values are non-negative here.
    const int y0 = (int)(b0 * (float)IMGH);
    const int x0 = (int)(b1 * (float)IMGW);
    const int y1 = (int)(b2 * (float)IMGH);
    const int x1 = (int)(b3 * (float)IMGW);
    const int ch = max(y1 - y0, 1);
    const int cw = max(x1 - x0, 1);

    const bool valid = (scores[0] >= 0.8f) && (scores[box] >= 0.8f) &&
                       (b1 >= 0.0f) && (b3 <= 1.0f);

    // ---- vertical taps for this output row p ----
    const float scale_h = (float)ch / (float)OUTSZ;
    const float src_h = ((float)p + 0.5f) * scale_h - 0.5f;
    const int base_h = (int)floorf(src_h) - 2;
    float wh[TAPS];
    int   ih[TAPS];
    float sh = 0.0f;
#pragma unroll
    for (int a = 0; a < TAPS; a++) {
        int t = base_h + a;
        float d = src_h - (float)t;
        float w = lanczos_w(d);
        wh[a] = w;
        sh += w;
        ih[a] = min(max(t, 0), ch - 1) + y0;
    }
    const float invh = 1.0f / sh;
#pragma unroll
    for (int a = 0; a < TAPS; a++) wh[a] *= invh;

    // ---- Stage A: vertical combine into shared row buffer (coalesced LDG) ----
    extern __shared__ float rowcomb[];  // cw * 3 floats (<= 2048*3)
    const int total = cw * 3;
    const int base_off = x0 * 3;
#pragma unroll 1
    for (int i = threadIdx.x; i < total; i += blockDim.x) {
        float acc = 0.0f;
#pragma unroll
        for (int a = 0; a < TAPS; a++) {
            acc = fmaf(wh[a], __ldg(&img[(size_t)ih[a] * (IMGW * 3) + base_off + i]), acc);
        }
        rowcomb[i] = acc;
    }
    __syncthreads();

    // ---- Stage B: horizontal combine from shared memory ----
    const float scale_w = (float)cw / (float)OUTSZ;
    for (int q = threadIdx.x; q < OUTSZ; q += blockDim.x) {
        const float src_w = ((float)q + 0.5f) * scale_w - 0.5f;
        const int base_w = (int)floorf(src_w) - 2;
        float ww[TAPS];
        int   iw[TAPS];
        float sw = 0.0f;
#pragma unroll
        for (int b = 0; b < TAPS; b++) {
            int t = base_w + b;
            float d = src_w - (float)t;
            float w = lanczos_w(d);
            ww[b] = w;
            sw += w;
            iw[b] = min(max(t, 0), cw - 1);
        }
        const float invw = valid ? (1.0f / sw) : 0.0f;  // fold validity mask

        float o0 = 0.0f, o1 = 0.0f, o2 = 0.0f;
#pragma unroll
        for (int b = 0; b < TAPS; b++) {
            float w = ww[b] * invw;
            int j = iw[b] * 3;
            o0 = fmaf(w, rowcomb[j + 0], o0);
            o1 = fmaf(w, rowcomb[j + 1], o1);
            o2 = fmaf(w, rowcomb[j + 2], o2);
        }
        size_t oidx = (((size_t)box * OUTSZ + p) * OUTSZ + q) * 3;
        out[oidx + 0] = o0;
        out[oidx + 1] = o1;
        out[oidx + 2] = o2;
    }
}

extern "C" void kernel_launch(void* const* d_in, const int* in_sizes, int n_in,
                              void* d_out, int out_size) {
    const float* scores = (const float*)d_in[0];   // (100,)
    const float* boxes  = (const float*)d_in[1];   // (100,4)
    const float* img    = (const float*)d_in[2];   // (1,2048,2048,3)
    float* out = (float*)d_out;                    // (10,260,260,3)

    dim3 grid(OUTSZ, 10);
    dim3 block(384);
    size_t smem = (size_t)IMGW * 3 * sizeof(float);  // 24576 B, max cw = 2048
    crop_resize_kernel<<<grid, block, smem>>>(scores, boxes, img, out);
}

// round 2
// speedup vs baseline: 1.7025x; 1.7025x over previous
#include <cuda_runtime.h>
#include <math.h>

#define OUTSZ 260
#define IMGW  2048
#define IMGH  2048
#define TAPS  6
#define NTHREADS 384

// Lanczos3 weights for 6 integer-spaced taps around src, using the identity
//   d_a = frac + (2 - a),  sin(pi*d_a) = (-1)^a * sin(pi*frac)
//   sin(pi*d_a/3) = sin(pi*frac/3 + pi*(2-a)/3)  (angle addition, fixed consts)
// w_a = sin(pi d)*sin(pi d/3)*3/(pi^2 d^2), normalized by the caller.
__device__ __forceinline__ void lanczos6(float frac, float* w) {
    const float sn = sinpif(frac);          // sin(pi*frac)
    const float su = sinpif(frac * (1.0f / 3.0f));
    const float cu = cospif(frac * (1.0f / 3.0f));
    const float R3 = 0.8660254037844386f;   // sqrt(3)/2
    // sin(pi*d_a/3) per tap a = 0..5
    float s3[TAPS];
    s3[0] = fmaf(su, -0.5f,  cu *  R3);
    s3[1] = fmaf(su,  0.5f,  cu *  R3);
    s3[2] = su;
    s3[3] = fmaf(su,  0.5f,  cu * -R3);
    s3[4] = fmaf(su, -0.5f,  cu * -R3);
    s3[5] = -su;
    const float C = 3.0f / (3.14159265358979323846f * 3.14159265358979323846f);
#pragma unroll
    for (int a = 0; a < TAPS; a++) {
        float d = frac + (float)(2 - a);
        float sgn = (a & 1) ? -sn : sn;
        float val = sgn * s3[a] * C / (d * d);
        w[a] = (fabsf(d) < 1e-8f) ? 1.0f : val;
    }
}

__global__ __launch_bounds__(NTHREADS)
void crop_resize_kernel(const float* __restrict__ scores,
                        const float* __restrict__ boxes,
                        const float* __restrict__ img,
                        float* __restrict__ out) {
    const int p   = blockIdx.x;   // output row 0..259
    const int box = blockIdx.y;   // 0..9

    const float b0 = boxes[box * 4 + 0];
    const float b1 = boxes[box * 4 + 1];
    const float b2 = boxes[box * 4 + 2];
    const float b3 = boxes[box * 4 + 3];
    // XLA f32->s32 convert truncates toward zero; values are non-negative here.
    const int y0 = (int)(b0 * (float)IMGH);
    const int x0 = (int)(b1 * (float)IMGW);
    const int y1 = (int)(b2 * (float)IMGH);
    const int x1 = (int)(b3 * (float)IMGW);
    const int ch = max(y1 - y0, 1);
    const int cw = max(x1 - x0, 1);

    const bool valid = (scores[0] >= 0.8f) && (scores[box] >= 0.8f) &&
                       (b1 >= 0.0f) && (b3 <= 1.0f);

    // ---- vertical taps for this output row p ----
    const float src_h = ((float)p + 0.5f) * ((float)ch / (float)OUTSZ) - 0.5f;
    const float fh = floorf(src_h);
    const int base_h = (int)fh - 2;
    float wh[TAPS];
    lanczos6(src_h - fh, wh);
    float sh = wh[0] + wh[1] + wh[2] + wh[3] + wh[4] + wh[5];
    const float invh = 1.0f / sh;
    const float4* rowp[TAPS];
#pragma unroll
    for (int a = 0; a < TAPS; a++) {
        wh[a] *= invh;
        int t = min(max(base_h + a, 0), ch - 1) + y0;
        rowp[a] = (const float4*)(img + (size_t)t * (IMGW * 3));
    }

    // ---- Stage A: vertical combine into shared row buffer (float4 LDG) ----
    extern __shared__ float smem_raw[];
    float* rc = smem_raw + 4;                 // 4-float front slack
    const int gbeg = x0 * 3;                  // first needed global float idx in row
    const int gend = gbeg + cw * 3;           // exclusive (<= 6144)
    const int gb4  = gbeg & ~3;               // aligned start (>= gbeg-3)
#pragma unroll 1
    for (int g = gb4 + 4 * threadIdx.x; g < gend; g += 4 * NTHREADS) {
        const int g4 = g >> 2;
        float4 acc = make_float4(0.f, 0.f, 0.f, 0.f);
#pragma unroll
        for (int a = 0; a < TAPS; a++) {
            float4 v = __ldg(rowp[a] + g4);
            acc.x = fmaf(wh[a], v.x, acc.x);
            acc.y = fmaf(wh[a], v.y, acc.y);
            acc.z = fmaf(wh[a], v.z, acc.z);
            acc.w = fmaf(wh[a], v.w, acc.w);
        }
        const int s = g - gbeg;               // may be -3..-1 for first chunk
        rc[s + 0] = acc.x;
        rc[s + 1] = acc.y;
        rc[s + 2] = acc.z;
        rc[s + 3] = acc.w;
    }
    __syncthreads();

    // ---- Stage B: horizontal combine from shared memory ----
    const float scale_w = (float)cw / (float)OUTSZ;
    for (int q = threadIdx.x; q < OUTSZ; q += NTHREADS) {
        const float src_w = ((float)q + 0.5f) * scale_w - 0.5f;
        const float fw = floorf(src_w);
        const int base_w = (int)fw - 2;
        float ww[TAPS];
        lanczos6(src_w - fw, ww);
        float sw = ww[0] + ww[1] + ww[2] + ww[3] + ww[4] + ww[5];
        const float invw = valid ? (1.0f / sw) : 0.0f;   // fold validity mask

        float o0 = 0.0f, o1 = 0.0f, o2 = 0.0f;
#pragma unroll
        for (int b = 0; b < TAPS; b++) {
            float w = ww[b] * invw;
            int j = min(max(base_w + b, 0), cw - 1) * 3;
            o0 = fmaf(w, rc[j + 0], o0);
            o1 = fmaf(w, rc[j + 1], o1);
            o2 = fmaf(w, rc[j + 2], o2);
        }
        size_t oidx = (((size_t)box * OUTSZ + p) * OUTSZ + q) * 3;
        out[oidx + 0] = o0;
        out[oidx + 1] = o1;
        out[oidx + 2] = o2;
    }
}

extern "C" void kernel_launch(void* const* d_in, const int* in_sizes, int n_in,
                              void* d_out, int out_size) {
    const float* scores = (const float*)d_in[0];   // (100,)
    const float* boxes  = (const float*)d_in[1];   // (100,4)
    const float* img    = (const float*)d_in[2];   // (1,2048,2048,3)
    float* out = (float*)d_out;                    // (10,260,260,3)

    dim3 grid(OUTSZ, 10);
    dim3 block(NTHREADS);
    size_t smem = (size_t)(4 + IMGW * 3 + 4) * sizeof(float);  // ~24.6 KB
    crop_resize_kernel<<<grid, block, smem>>>(scores, boxes, img, out);
}